// round 16
// baseline (speedup 1.0000x reference)
#include <cuda_runtime.h>
#include <float.h>

// Problem shape (fixed by the dataset)
#define BB    32
#define LL    8192
#define DD    256
#define TOPK  8
#define CHUNK 256
#define SS    (LL / CHUNK)     // 32 chunks along L
#define MB    8                // merge blocks per batch

// Scratch (device globals: no allocation allowed anywhere)
__device__ float g_part[(size_t)BB * SS * DD * TOPK];  // 8.4 MB
__device__ int   g_nchunk[BB];  // valid chunks per batch (replay-invariant)
__device__ int   g_cnt[BB];     // stored-chunk arrivals (reset each replay)
__device__ int   g_done[BB];    // merge-block completion tickets (reset each replay)

#define NEG (-FLT_MAX)

// Compare-exchange, descending (a keeps max). 2 FMNMX, no branches.
#define CE(a, b) { float _hi = fmaxf(a, b); float _lo = fminf(a, b); (a) = _hi; (b) = _lo; }

// Batcher odd-even sort-8, descending. 19 CE = 38 ops (optimal CE count).
__device__ __forceinline__ void sort8(float (&s)[8]) {
    CE(s[0], s[1]); CE(s[2], s[3]); CE(s[4], s[5]); CE(s[6], s[7]);
    CE(s[0], s[2]); CE(s[1], s[3]); CE(s[4], s[6]); CE(s[5], s[7]);
    CE(s[1], s[2]); CE(s[5], s[6]);
    CE(s[0], s[4]); CE(s[1], s[5]); CE(s[2], s[6]); CE(s[3], s[7]);
    CE(s[2], s[4]); CE(s[3], s[5]);
    CE(s[1], s[2]); CE(s[3], s[4]); CE(s[5], s[6]);
}

// Merge sorted-desc 8-list s into sorted-desc accumulator v (exact top-8 of
// the union). Partner stage (8 ops) + 3-stage bitonic merge-8 (24 ops).
__device__ __forceinline__ void acc8(float (&v)[8], const float (&s)[8]) {
    v[0] = fmaxf(v[0], s[7]); v[1] = fmaxf(v[1], s[6]);
    v[2] = fmaxf(v[2], s[5]); v[3] = fmaxf(v[3], s[4]);
    v[4] = fmaxf(v[4], s[3]); v[5] = fmaxf(v[5], s[2]);
    v[6] = fmaxf(v[6], s[1]); v[7] = fmaxf(v[7], s[0]);
    CE(v[0], v[4]); CE(v[1], v[5]); CE(v[2], v[6]); CE(v[3], v[7]);
    CE(v[0], v[2]); CE(v[1], v[3]); CE(v[4], v[6]); CE(v[5], v[7]);
    CE(v[0], v[1]); CE(v[2], v[3]); CE(v[4], v[5]); CE(v[6], v[7]);
}

// ---------------------------------------------------------------------------
// Single kernel, grid (32, 40) x 256 threads.
//   y < BB : partial block (chunk s = x, batch b = y). ONE CHANNEL PER
//            THREAD: thread tid owns channel d = tid for the whole 256-row
//            chunk. Scalar loads (warp = 128B contiguous per row), 8-row
//            sort8+acc8 batches, ~16 live value regs -> high occupancy.
//            All control flow is block-uniform (nvalid is block-wide).
//   y >= BB: merge block (batch b = x, channel group m = y-BB), launched at
//            the end of the linear block order so it never steals wave-1
//            slots. Spins until its batch's chunks are all stored, then
//            merges the nc chunk-lists and writes the output.
// Sync: storing partial blocks {stores; threadfence; syncthreads; atomicAdd
// g_cnt[b]}. The boundary chunk publishes g_nchunk[b] before its own fenced
// increment, so g_cnt[b]==g_nchunk[b] implies all scratch visible. Merge
// blocks ticket through g_done[b]; ticket MB-1 resets both counters so graph
// replays start clean (g_nchunk is replay-invariant; stale == correct).
// Deadlock-free: partial blocks never wait.
// ---------------------------------------------------------------------------
__global__ __launch_bounds__(256) void topk_kernel(const float* __restrict__ x,
                                                   const int* __restrict__ mask,
                                                   float* __restrict__ out) {
    __shared__ float msh[DD][TOPK + 1];   // merge: seg combine (+1 pad)
    __shared__ int   wcnt[8];
    __shared__ int   s_nc;

    int tid = threadIdx.x;

    if (blockIdx.y >= BB) {
        // ---------------- merge block ----------------
        int b   = blockIdx.x;
        int m   = blockIdx.y - BB;          // channel group of 32
        int c   = tid & 31;
        int seg = tid >> 5;                 // 0..7
        int d   = m * 32 + c;

        if (tid == 0) {
            volatile int* vn = &g_nchunk[b];
            int nc;
            while ((nc = *vn) == 0) __nanosleep(64);
            while (atomicAdd(&g_cnt[b], 0) < nc) __nanosleep(64);
            s_nc = nc;
        }
        __syncthreads();
        __threadfence();                    // acquire: scratch stores visible
        int nc = s_nc;

        int p0 = (seg * nc) >> 3;
        int p1 = ((seg + 1) * nc) >> 3;
        const float* base = g_part + ((size_t)b * SS * DD + d) * TOPK;

        float v[8];
        #pragma unroll
        for (int j = 0; j < 8; ++j) v[j] = NEG;
        for (int p = p0; p < p1; ++p) {
            const float4* c4 = reinterpret_cast<const float4*>(base + (size_t)p * DD * TOPK);
            float4 a = __ldg(c4);
            float4 e = __ldg(c4 + 1);
            float t[8] = {a.x, a.y, a.z, a.w, e.x, e.y, e.z, e.w};  // sorted desc
            acc8(v, t);
        }

        #pragma unroll
        for (int j = 0; j < 8; ++j) msh[seg * 32 + c][j] = v[j];
        __syncthreads();
        if (seg == 0) {
            #pragma unroll
            for (int s2 = 1; s2 < 8; ++s2) {
                float t[8];
                #pragma unroll
                for (int j = 0; j < 8; ++j) t[j] = msh[s2 * 32 + c][j];
                acc8(v, t);
            }
            #pragma unroll
            for (int k = 0; k < TOPK; ++k)
                out[(size_t)b * TOPK * DD + (size_t)k * DD + d] = v[k];
        }
        __syncthreads();
        if (tid == 0) {
            int t = atomicAdd(&g_done[b], 1);
            if (t == MB - 1) { g_cnt[b] = 0; g_done[b] = 0; }  // clean for replay
        }
        return;
    }

    // ---------------- partial block: one channel per thread ----------------
    int b  = blockIdx.y;
    int s  = blockIdx.x;
    int lo = s * CHUNK;

    // nvalid for this chunk from its own mask rows (monotone 0...0 1...1)
    int m = mask[(size_t)b * LL + lo + tid];
    unsigned bal = __ballot_sync(0xffffffffu, m == 0);
    if ((tid & 31) == 0) wcnt[tid >> 5] = __popc(bal);
    __syncthreads();
    int nvalid = 0;
    #pragma unroll
    for (int w = 0; w < 8; ++w) nvalid += wcnt[w];

    // Publish the valid-chunk count: exactly one block per batch qualifies.
    // Ordered before this block's fenced g_cnt increment below.
    if (tid == 0 && nvalid > 0) {
        bool last;
        if (nvalid < CHUNK)      last = true;
        else if (s == SS - 1)    last = true;
        else                     last = (mask[(size_t)b * LL + lo + CHUNK] == 1);
        if (last) g_nchunk[b] = s + 1;
    }
    if (nvalid == 0) return;   // never stores, never counted, never read

    int nfull = nvalid >> 3;   // block-uniform: zero divergence below
    int rem   = nvalid & 7;

    float v[8];
    #pragma unroll
    for (int j = 0; j < 8; ++j) v[j] = NEG;

    const float* px = x + ((size_t)b * LL + lo) * DD + tid;   // channel = tid

    #pragma unroll 1
    for (int it = 0; it < nfull; ++it) {
        float t[8];
        #pragma unroll
        for (int j = 0; j < 8; ++j) t[j] = __ldcs(px + (size_t)j * DD);
        px += 8 * DD;
        sort8(t);
        acc8(v, t);
    }
    if (rem) {   // block-uniform; rows exist in memory (within chunk), just masked
        float t[8];
        #pragma unroll
        for (int j = 0; j < 8; ++j)
            t[j] = (j < rem) ? __ldcs(px + (size_t)j * DD) : NEG;
        sort8(t);
        acc8(v, t);
    }

    // 32B per thread, contiguous across threads -> coalesced 8KB per block
    float* dst = g_part + (((size_t)b * SS + s) * DD + tid) * TOPK;
    #pragma unroll
    for (int j = 0; j < TOPK; ++j) dst[j] = v[j];

    // Release: scratch (and g_nchunk if boundary) visible before the count.
    __threadfence();
    __syncthreads();                 // all stores in this block issued
    if (tid == 0) atomicAdd(&g_cnt[b], 1);
}

extern "C" void kernel_launch(void* const* d_in, const int* in_sizes, int n_in,
                              void* d_out, int out_size) {
    const float* x    = (const float*)d_in[0];
    const int*   mask = (const int*)d_in[1];
    float*       out  = (float*)d_out;

    topk_kernel<<<dim3(SS, BB + MB), 256>>>(x, mask, out);
}